// round 3
// baseline (speedup 1.0000x reference)
#include <cuda_runtime.h>
#include <cstdint>

// Integrator: y[b,c,n] = cumsum over time axis. 32 independent rows, T = 2^20.
// Single-pass tile scan with a published-aggregate spine (deterministic:
// every tile sums ALL predecessor aggregates with a fixed grouping).
//
// R2 changes: TILE 2048->4096 (8 spine entries/lane max), MLP'd batched
// polling (loads issued in parallel per round), streaming cache hints.

#define THREADS 256
#define ITEMS 16
#define TILE (THREADS * ITEMS)          // 4096
#define T_LEN 1048576
#define TILES_PER_ROW (T_LEN / TILE)    // 256 (power of two)
#define MAX_TILES 8192                  // 32 rows * 256

// Spine: flag (hi 32) | float bits (lo 32). flag: 0 = invalid, 1 = aggregate.
__device__ unsigned long long g_spine[MAX_TILES];

__global__ void integrator_init_kernel(int ntiles) {
    int i = blockIdx.x * blockDim.x + threadIdx.x;
    if (i < ntiles) g_spine[i] = 0ULL;
}

__device__ __forceinline__ unsigned long long pack_agg(float v) {
    return (1ULL << 32) | (unsigned long long)__float_as_uint(v);
}

__device__ __forceinline__ void spine_publish(unsigned long long* p, unsigned long long v) {
    asm volatile("st.global.relaxed.gpu.b64 [%0], %1;" :: "l"(p), "l"(v) : "memory");
}

__device__ __forceinline__ unsigned long long spine_poll(const unsigned long long* p) {
    unsigned long long v;
    asm volatile("ld.global.relaxed.gpu.b64 %0, [%1];" : "=l"(v) : "l"(p) : "memory");
    return v;
}

__global__ __launch_bounds__(THREADS, 6)
void integrator_scan_kernel(const float* __restrict__ x, float* __restrict__ y) {
    __shared__ float s_warp[8];      // warp inclusive totals
    __shared__ float s_woff[8];      // exclusive warp offsets within tile
    __shared__ float s_excl;         // exclusive prefix of this tile within its row

    const int bid = blockIdx.x;
    const int tile_in_row = bid & (TILES_PER_ROW - 1);
    const long long base = (long long)bid * TILE;

    const int t = threadIdx.x;
    const int lane = t & 31;
    const int warp = t >> 5;

    // ---- load 16 contiguous items per thread (four float4), streaming ----
    const float4* xv = reinterpret_cast<const float4*>(x + base);
    float4 a0 = __ldcs(xv + t * 4 + 0);
    float4 a1 = __ldcs(xv + t * 4 + 1);
    float4 a2 = __ldcs(xv + t * 4 + 2);
    float4 a3 = __ldcs(xv + t * 4 + 3);

    // thread-local inclusive scan (in place)
    a0.y += a0.x; a0.z += a0.y; a0.w += a0.z;
    a1.x += a0.w; a1.y += a1.x; a1.z += a1.y; a1.w += a1.z;
    a2.x += a1.w; a2.y += a2.x; a2.z += a2.y; a2.w += a2.z;
    a3.x += a2.w; a3.y += a3.x; a3.z += a3.y; a3.w += a3.z;
    const float tot = a3.w;

    // warp inclusive scan of per-thread totals
    float incl = tot;
    #pragma unroll
    for (int d = 1; d < 32; d <<= 1) {
        float n = __shfl_up_sync(0xffffffffu, incl, d);
        if (lane >= d) incl += n;
    }
    if (lane == 31) s_warp[warp] = incl;
    const float thr_excl = incl - tot;   // exclusive offset within warp

    __syncthreads();

    if (warp == 0) {
        // scan the 8 warp totals
        float w = (lane < 8) ? s_warp[lane] : 0.0f;
        float wincl = w;
        #pragma unroll
        for (int d = 1; d < 8; d <<= 1) {
            float n = __shfl_up_sync(0xffffffffu, wincl, d);
            if (lane >= d) wincl += n;
        }
        if (lane < 8) s_woff[lane] = wincl - w;
        const float blocktot = __shfl_sync(0xffffffffu, wincl, 7);

        // publish this tile's aggregate ASAP (single 64-bit word: no fence needed)
        if (lane == 0) spine_publish(&g_spine[bid], pack_agg(blocktot));

        // Deterministic spine accumulation: sum ALL predecessor aggregates.
        // lane l owns tiles {l, l+32, ..} < tile_in_row (<=8 entries each).
        // Polling is batched: all still-pending loads of a round are issued
        // back-to-back (MLP), flags checked afterwards.
        float excl = 0.0f;
        if (tile_in_row > 0) {
            const int rowbase = bid - tile_in_row;
            const int cnt = (tile_in_row > lane) ? ((tile_in_row - lane + 31) >> 5) : 0;
            float v[8];
            unsigned pend = (cnt > 0) ? ((1u << cnt) - 1u) : 0u;
            while (pend) {
                unsigned long long w8[8];
                #pragma unroll
                for (int i = 0; i < 8; i++)
                    if (pend & (1u << i))
                        w8[i] = spine_poll(&g_spine[rowbase + lane + 32 * i]);
                #pragma unroll
                for (int i = 0; i < 8; i++)
                    if ((pend & (1u << i)) && (unsigned)(w8[i] >> 32)) {
                        v[i] = __uint_as_float((unsigned)w8[i]);
                        pend &= ~(1u << i);
                    }
            }
            float lsum = 0.0f;
            #pragma unroll
            for (int i = 0; i < 8; i++)
                if (i < cnt) lsum += v[i];
            #pragma unroll
            for (int d = 16; d; d >>= 1)
                lsum += __shfl_xor_sync(0xffffffffu, lsum, d);
            excl = lsum;
        }
        if (lane == 0) s_excl = excl;
    }

    __syncthreads();

    const float off = s_excl + s_woff[warp] + thr_excl;

    float4* yv = reinterpret_cast<float4*>(y + base);
    a0.x += off; a0.y += off; a0.z += off; a0.w += off;
    a1.x += off; a1.y += off; a1.z += off; a1.w += off;
    a2.x += off; a2.y += off; a2.z += off; a2.w += off;
    a3.x += off; a3.y += off; a3.z += off; a3.w += off;
    __stcs(yv + t * 4 + 0, a0);
    __stcs(yv + t * 4 + 1, a1);
    __stcs(yv + t * 4 + 2, a2);
    __stcs(yv + t * 4 + 3, a3);
}

extern "C" void kernel_launch(void* const* d_in, const int* in_sizes, int n_in,
                              void* d_out, int out_size) {
    const float* x = (const float*)d_in[0];
    float* y = (float*)d_out;

    const int n = out_size;              // 8*4*1048576 = 33554432
    const int ntiles = n / TILE;         // 8192

    integrator_init_kernel<<<(ntiles + 255) / 256, 256>>>(ntiles);
    integrator_scan_kernel<<<ntiles, THREADS>>>(x, y);
}

// round 4
// speedup vs baseline: 1.0186x; 1.0186x over previous
#include <cuda_runtime.h>
#include <cstdint>

// Integrator: y[b,c,n] = cumsum over time axis. 32 independent rows, T = 2^20.
// Single-pass tile scan with a published-aggregate spine (deterministic:
// every tile sums ALL predecessor aggregates with a fixed grouping).
//
// R2 changes: TILE 2048->4096 (8 spine entries/lane max), MLP'd batched
// polling (loads issued in parallel per round), streaming cache hints.

#define THREADS 256
#define ITEMS 16
#define TILE (THREADS * ITEMS)          // 4096
#define T_LEN 1048576
#define TILES_PER_ROW (T_LEN / TILE)    // 256 (power of two)
#define MAX_TILES 8192                  // 32 rows * 256

// Spine: flag (hi 32) | float bits (lo 32). flag: 0 = invalid, 1 = aggregate.
__device__ unsigned long long g_spine[MAX_TILES];

__global__ void integrator_init_kernel(int ntiles) {
    int i = blockIdx.x * blockDim.x + threadIdx.x;
    if (i < ntiles) g_spine[i] = 0ULL;
}

__device__ __forceinline__ unsigned long long pack_agg(float v) {
    return (1ULL << 32) | (unsigned long long)__float_as_uint(v);
}

__device__ __forceinline__ void spine_publish(unsigned long long* p, unsigned long long v) {
    asm volatile("st.global.relaxed.gpu.b64 [%0], %1;" :: "l"(p), "l"(v) : "memory");
}

__device__ __forceinline__ unsigned long long spine_poll(const unsigned long long* p) {
    unsigned long long v;
    asm volatile("ld.global.relaxed.gpu.b64 %0, [%1];" : "=l"(v) : "l"(p) : "memory");
    return v;
}

__global__ __launch_bounds__(THREADS, 6)
void integrator_scan_kernel(const float* __restrict__ x, float* __restrict__ y) {
    __shared__ float s_warp[8];      // warp inclusive totals
    __shared__ float s_woff[8];      // exclusive warp offsets within tile
    __shared__ float s_excl;         // exclusive prefix of this tile within its row

    const int bid = blockIdx.x;
    const int tile_in_row = bid & (TILES_PER_ROW - 1);
    const long long base = (long long)bid * TILE;

    const int t = threadIdx.x;
    const int lane = t & 31;
    const int warp = t >> 5;

    // ---- load 16 contiguous items per thread (four float4), streaming ----
    const float4* xv = reinterpret_cast<const float4*>(x + base);
    float4 a0 = __ldcs(xv + t * 4 + 0);
    float4 a1 = __ldcs(xv + t * 4 + 1);
    float4 a2 = __ldcs(xv + t * 4 + 2);
    float4 a3 = __ldcs(xv + t * 4 + 3);

    // thread-local inclusive scan (in place)
    a0.y += a0.x; a0.z += a0.y; a0.w += a0.z;
    a1.x += a0.w; a1.y += a1.x; a1.z += a1.y; a1.w += a1.z;
    a2.x += a1.w; a2.y += a2.x; a2.z += a2.y; a2.w += a2.z;
    a3.x += a2.w; a3.y += a3.x; a3.z += a3.y; a3.w += a3.z;
    const float tot = a3.w;

    // warp inclusive scan of per-thread totals
    float incl = tot;
    #pragma unroll
    for (int d = 1; d < 32; d <<= 1) {
        float n = __shfl_up_sync(0xffffffffu, incl, d);
        if (lane >= d) incl += n;
    }
    if (lane == 31) s_warp[warp] = incl;
    const float thr_excl = incl - tot;   // exclusive offset within warp

    __syncthreads();

    if (warp == 0) {
        // scan the 8 warp totals
        float w = (lane < 8) ? s_warp[lane] : 0.0f;
        float wincl = w;
        #pragma unroll
        for (int d = 1; d < 8; d <<= 1) {
            float n = __shfl_up_sync(0xffffffffu, wincl, d);
            if (lane >= d) wincl += n;
        }
        if (lane < 8) s_woff[lane] = wincl - w;
        const float blocktot = __shfl_sync(0xffffffffu, wincl, 7);

        // publish this tile's aggregate ASAP (single 64-bit word: no fence needed)
        if (lane == 0) spine_publish(&g_spine[bid], pack_agg(blocktot));

        // Deterministic spine accumulation: sum ALL predecessor aggregates.
        // lane l owns tiles {l, l+32, ..} < tile_in_row (<=8 entries each).
        // Polling is batched: all still-pending loads of a round are issued
        // back-to-back (MLP), flags checked afterwards.
        float excl = 0.0f;
        if (tile_in_row > 0) {
            const int rowbase = bid - tile_in_row;
            const int cnt = (tile_in_row > lane) ? ((tile_in_row - lane + 31) >> 5) : 0;
            float v[8];
            unsigned pend = (cnt > 0) ? ((1u << cnt) - 1u) : 0u;
            while (pend) {
                unsigned long long w8[8];
                #pragma unroll
                for (int i = 0; i < 8; i++)
                    if (pend & (1u << i))
                        w8[i] = spine_poll(&g_spine[rowbase + lane + 32 * i]);
                #pragma unroll
                for (int i = 0; i < 8; i++)
                    if ((pend & (1u << i)) && (unsigned)(w8[i] >> 32)) {
                        v[i] = __uint_as_float((unsigned)w8[i]);
                        pend &= ~(1u << i);
                    }
            }
            float lsum = 0.0f;
            #pragma unroll
            for (int i = 0; i < 8; i++)
                if (i < cnt) lsum += v[i];
            #pragma unroll
            for (int d = 16; d; d >>= 1)
                lsum += __shfl_xor_sync(0xffffffffu, lsum, d);
            excl = lsum;
        }
        if (lane == 0) s_excl = excl;
    }

    __syncthreads();

    const float off = s_excl + s_woff[warp] + thr_excl;

    float4* yv = reinterpret_cast<float4*>(y + base);
    a0.x += off; a0.y += off; a0.z += off; a0.w += off;
    a1.x += off; a1.y += off; a1.z += off; a1.w += off;
    a2.x += off; a2.y += off; a2.z += off; a2.w += off;
    a3.x += off; a3.y += off; a3.z += off; a3.w += off;
    __stcs(yv + t * 4 + 0, a0);
    __stcs(yv + t * 4 + 1, a1);
    __stcs(yv + t * 4 + 2, a2);
    __stcs(yv + t * 4 + 3, a3);
}

extern "C" void kernel_launch(void* const* d_in, const int* in_sizes, int n_in,
                              void* d_out, int out_size) {
    const float* x = (const float*)d_in[0];
    float* y = (float*)d_out;

    const int n = out_size;              // 8*4*1048576 = 33554432
    const int ntiles = n / TILE;         // 8192

    integrator_init_kernel<<<(ntiles + 255) / 256, 256>>>(ntiles);
    integrator_scan_kernel<<<ntiles, THREADS>>>(x, y);
}

// round 5
// speedup vs baseline: 1.2284x; 1.2059x over previous
#include <cuda_runtime.h>
#include <cstdint>

// Integrator: y[b,c,n] = cumsum over time axis. 32 rows, T = 2^20.
//
// R5 architecture: single-wave two-phase blocks.
//   1024 blocks x 32K elements. Phase A: segment sum (independent, BW-bound),
//   publish aggregate. Lookback: <=31 predecessors, 1 per lane, 1 round.
//   Phase B: re-read (mostly L2-hit), block-scan in 8 chunks, store.

#define THREADS 256
#define SEG 32768                      // elements per block
#define CHUNK 4096                     // elements per phase-B chunk (256*16)
#define NCHUNK (SEG / CHUNK)           // 8
#define F4_PER_SEG (SEG / 4)           // 8192
#define F4_PER_CHUNK (CHUNK / 4)       // 1024
#define T_LEN 1048576
#define SEGS_PER_ROW (T_LEN / SEG)     // 32 (power of two)
#define NSEG 1024                      // 32 rows * 32 segments

// Spine: flag (hi 32) | float bits (lo 32).
__device__ unsigned long long g_spine[NSEG];

__global__ void integrator_init_kernel() {
    int i = blockIdx.x * blockDim.x + threadIdx.x;
    if (i < NSEG) g_spine[i] = 0ULL;
}

__device__ __forceinline__ void spine_publish(unsigned long long* p, float v) {
    unsigned long long w = (1ULL << 32) | (unsigned long long)__float_as_uint(v);
    asm volatile("st.global.relaxed.gpu.b64 [%0], %1;" :: "l"(p), "l"(w) : "memory");
}

__device__ __forceinline__ unsigned long long spine_poll(const unsigned long long* p) {
    unsigned long long v;
    asm volatile("ld.global.relaxed.gpu.b64 %0, [%1];" : "=l"(v) : "l"(p) : "memory");
    return v;
}

__global__ __launch_bounds__(THREADS, 7)
void integrator_scan_kernel(const float* __restrict__ x, float* __restrict__ y) {
    __shared__ float s_warp[8];      // per-warp totals (per chunk)
    __shared__ float s_woff[8];      // exclusive warp offsets within chunk
    __shared__ float s_ctot;         // chunk total
    __shared__ float s_excl;         // exclusive prefix of this segment

    const int bid = blockIdx.x;
    const int seg_in_row = bid & (SEGS_PER_ROW - 1);
    const long long base = (long long)bid * SEG;

    const int t = threadIdx.x;
    const int lane = t & 31;
    const int warp = t >> 5;

    const float4* xv = reinterpret_cast<const float4*>(x + base);
    float4* yv = reinterpret_cast<float4*>(y + base);

    // ===== Phase A: segment sum (independent streaming reads, fill L2) =====
    float s0 = 0.f, s1 = 0.f, s2 = 0.f, s3 = 0.f;
    #pragma unroll 4
    for (int c = 0; c < F4_PER_SEG / THREADS; c++) {   // 32 iters
        float4 v = xv[c * THREADS + t];
        s0 += v.x; s1 += v.y; s2 += v.z; s3 += v.w;
    }
    float tsum = (s0 + s1) + (s2 + s3);
    #pragma unroll
    for (int d = 16; d; d >>= 1)
        tsum += __shfl_xor_sync(0xffffffffu, tsum, d);
    if (lane == 0) s_warp[warp] = tsum;
    __syncthreads();

    if (warp == 0) {
        float w = (lane < 8) ? s_warp[lane] : 0.0f;
        #pragma unroll
        for (int d = 4; d; d >>= 1)
            w += __shfl_xor_sync(0xffffffffu, w, d);
        // w = block total in every lane of the low 8; take lane 0's value
        float blocktot = __shfl_sync(0xffffffffu, w, 0);

        if (lane == 0) spine_publish(&g_spine[bid], blocktot);

        // Lookback: <=31 predecessors, one per lane, single round + fixed reduce.
        float excl = 0.0f;
        if (seg_in_row > 0) {
            float v = 0.0f;
            if (lane < seg_in_row) {
                const unsigned long long* p = &g_spine[bid - seg_in_row + lane];
                unsigned long long e;
                do { e = spine_poll(p); } while ((unsigned)(e >> 32) == 0u);
                v = __uint_as_float((unsigned)e);
            }
            #pragma unroll
            for (int d = 16; d; d >>= 1)
                v += __shfl_xor_sync(0xffffffffu, v, d);
            excl = v;
        }
        if (lane == 0) s_excl = excl;
    }
    __syncthreads();

    // ===== Phase B: scan segment in 8 chunks (re-reads mostly hit L2) =====
    float carry = s_excl;

    for (int c = 0; c < NCHUNK; c++) {
        const int cb = c * F4_PER_CHUNK;   // float4 base of this chunk

        float4 a0 = xv[cb + t * 4 + 0];
        float4 a1 = xv[cb + t * 4 + 1];
        float4 a2 = xv[cb + t * 4 + 2];
        float4 a3 = xv[cb + t * 4 + 3];

        // thread-local inclusive scan of 16
        a0.y += a0.x; a0.z += a0.y; a0.w += a0.z;
        a1.x += a0.w; a1.y += a1.x; a1.z += a1.y; a1.w += a1.z;
        a2.x += a1.w; a2.y += a2.x; a2.z += a2.y; a2.w += a2.z;
        a3.x += a2.w; a3.y += a3.x; a3.z += a3.y; a3.w += a3.z;
        const float tot = a3.w;

        // warp inclusive scan of per-thread totals
        float incl = tot;
        #pragma unroll
        for (int d = 1; d < 32; d <<= 1) {
            float n = __shfl_up_sync(0xffffffffu, incl, d);
            if (lane >= d) incl += n;
        }
        if (lane == 31) s_warp[warp] = incl;
        const float thr_excl = incl - tot;

        __syncthreads();

        if (warp == 0) {
            float w = (lane < 8) ? s_warp[lane] : 0.0f;
            float wincl = w;
            #pragma unroll
            for (int d = 1; d < 8; d <<= 1) {
                float n = __shfl_up_sync(0xffffffffu, wincl, d);
                if (lane >= d) wincl += n;
            }
            if (lane < 8) s_woff[lane] = wincl - w;
            if (lane == 7) s_ctot = wincl;
        }

        __syncthreads();

        const float off = carry + s_woff[warp] + thr_excl;

        a0.x += off; a0.y += off; a0.z += off; a0.w += off;
        a1.x += off; a1.y += off; a1.z += off; a1.w += off;
        a2.x += off; a2.y += off; a2.z += off; a2.w += off;
        a3.x += off; a3.y += off; a3.z += off; a3.w += off;
        __stcs(yv + cb + t * 4 + 0, a0);
        __stcs(yv + cb + t * 4 + 1, a1);
        __stcs(yv + cb + t * 4 + 2, a2);
        __stcs(yv + cb + t * 4 + 3, a3);

        carry += s_ctot;
    }
}

extern "C" void kernel_launch(void* const* d_in, const int* in_sizes, int n_in,
                              void* d_out, int out_size) {
    const float* x = (const float*)d_in[0];
    float* y = (float*)d_out;

    const int n = out_size;              // 33554432
    const int nseg = n / SEG;            // 1024

    integrator_init_kernel<<<2, 512>>>();
    integrator_scan_kernel<<<nseg, THREADS>>>(x, y);
}

// round 6
// speedup vs baseline: 1.2899x; 1.0501x over previous
#include <cuda_runtime.h>
#include <cstdint>

// Integrator: y[b,c,n] = cumsum over time axis. 32 rows, T = 2^20.
//
// R6: smem-staged single-read scan.
//   4096 blocks x 8192 elements. Phase A: load once (streaming), thread-local
//   running scan into padded smem, one combined (chunk,warp) offset scan.
//   Publish aggregate -> deterministic batched lookback (<=4 entries/lane).
//   Phase B: read scanned values from smem, add offset, streaming store.
//   DRAM traffic = 256 MB (the floor).

#define THREADS 256
#define SEG 8192                        // elements per block
#define NCHUNK 2                        // chunks of 4096
#define F4_PER_CHUNK 1024
#define T_LEN 1048576
#define SEGS_PER_ROW (T_LEN / SEG)      // 128 (power of two)
#define NSEG 4096                       // 32 rows * 128
#define SMEM_FLOATS (SEG + SEG / 16)    // 8704 (pad 1 float per 16)

// Spine: flag (hi 32) | float bits (lo 32).
__device__ unsigned long long g_spine[NSEG];

__global__ void integrator_init_kernel() {
    int i = blockIdx.x * blockDim.x + threadIdx.x;
    if (i < NSEG) g_spine[i] = 0ULL;
}

__device__ __forceinline__ void spine_publish(unsigned long long* p, float v) {
    unsigned long long w = (1ULL << 32) | (unsigned long long)__float_as_uint(v);
    asm volatile("st.global.relaxed.gpu.b64 [%0], %1;" :: "l"(p), "l"(w) : "memory");
}

__device__ __forceinline__ unsigned long long spine_poll(const unsigned long long* p) {
    unsigned long long v;
    asm volatile("ld.global.relaxed.gpu.b64 %0, [%1];" : "=l"(v) : "l"(p) : "memory");
    return v;
}

__global__ __launch_bounds__(THREADS, 4)
void integrator_scan_kernel(const float* __restrict__ x, float* __restrict__ y) {
    __shared__ float s_data[SMEM_FLOATS];   // padded scanned values
    __shared__ float s_cw[16];              // (chunk,warp) totals, idx = c*8+w
    __shared__ float s_off[16];             // exclusive offsets for (chunk,warp)
    __shared__ float s_excl;                // exclusive prefix of this segment

    const int bid = blockIdx.x;
    const int seg_in_row = bid & (SEGS_PER_ROW - 1);
    const long long base = (long long)bid * SEG;

    const int t = threadIdx.x;
    const int lane = t & 31;
    const int warp = t >> 5;

    const float4* xv = reinterpret_cast<const float4*>(x + base);
    float4* yv = reinterpret_cast<float4*>(y + base);

    // ===== Phase A: single read, thread-local running scan into smem =====
    float tc[NCHUNK];        // per-chunk thread totals
    float texcl[NCHUNK];     // per-chunk exclusive offset of thread within warp

    #pragma unroll
    for (int c = 0; c < NCHUNK; c++) {
        const int fb = c * F4_PER_CHUNK + t * 4;
        float4 a0 = __ldcs(xv + fb + 0);
        float4 a1 = __ldcs(xv + fb + 1);
        float4 a2 = __ldcs(xv + fb + 2);
        float4 a3 = __ldcs(xv + fb + 3);

        // running inclusive scan of the thread's 16 contiguous elements
        float r = a0.x;
        float* sb = s_data + c * 4352 + t * 17;   // padded base (conflict-free)
        sb[0] = r;
        r += a0.y; sb[1] = r;  r += a0.z; sb[2] = r;  r += a0.w; sb[3] = r;
        r += a1.x; sb[4] = r;  r += a1.y; sb[5] = r;  r += a1.z; sb[6] = r;  r += a1.w; sb[7] = r;
        r += a2.x; sb[8] = r;  r += a2.y; sb[9] = r;  r += a2.z; sb[10] = r; r += a2.w; sb[11] = r;
        r += a3.x; sb[12] = r; r += a3.y; sb[13] = r; r += a3.z; sb[14] = r; r += a3.w; sb[15] = r;
        tc[c] = r;
    }

    // warp inclusive scan of thread totals, per chunk
    #pragma unroll
    for (int c = 0; c < NCHUNK; c++) {
        float incl = tc[c];
        #pragma unroll
        for (int d = 1; d < 32; d <<= 1) {
            float n = __shfl_up_sync(0xffffffffu, incl, d);
            if (lane >= d) incl += n;
        }
        texcl[c] = incl - tc[c];
        if (lane == 31) s_cw[c * 8 + warp] = incl;
    }

    __syncthreads();

    if (warp == 0) {
        // one warp scan over all 16 (chunk,warp) totals in segment order
        float v = (lane < 16) ? s_cw[lane] : 0.0f;
        float incl = v;
        #pragma unroll
        for (int d = 1; d < 16; d <<= 1) {
            float n = __shfl_up_sync(0xffffffffu, incl, d);
            if (lane >= d) incl += n;
        }
        if (lane < 16) s_off[lane] = incl - v;
        const float blocktot = __shfl_sync(0xffffffffu, incl, 15);

        if (lane == 0) spine_publish(&g_spine[bid], blocktot);

        // Deterministic lookback: <=127 predecessors, <=4 per lane,
        // MLP-batched polling, fixed-grouping reduce.
        float excl = 0.0f;
        if (seg_in_row > 0) {
            const int rowbase = bid - seg_in_row;
            const int cnt = (seg_in_row > lane) ? ((seg_in_row - lane + 31) >> 5) : 0;
            float v4[4];
            unsigned pend = (cnt > 0) ? ((1u << cnt) - 1u) : 0u;
            while (pend) {
                unsigned long long w4[4];
                #pragma unroll
                for (int i = 0; i < 4; i++)
                    if (pend & (1u << i))
                        w4[i] = spine_poll(&g_spine[rowbase + lane + 32 * i]);
                #pragma unroll
                for (int i = 0; i < 4; i++)
                    if ((pend & (1u << i)) && (unsigned)(w4[i] >> 32)) {
                        v4[i] = __uint_as_float((unsigned)w4[i]);
                        pend &= ~(1u << i);
                    }
            }
            float lsum = 0.0f;
            #pragma unroll
            for (int i = 0; i < 4; i++)
                if (i < cnt) lsum += v4[i];
            #pragma unroll
            for (int d = 16; d; d >>= 1)
                lsum += __shfl_xor_sync(0xffffffffu, lsum, d);
            excl = lsum;
        }
        if (lane == 0) s_excl = excl;
    }

    __syncthreads();

    // ===== Phase B: smem -> registers -> global (streaming stores) =====
    const float seg_excl = s_excl;
    #pragma unroll
    for (int c = 0; c < NCHUNK; c++) {
        const float off = seg_excl + s_off[c * 8 + warp] + texcl[c];
        const float* sb = s_data + c * 4352 + t * 17;
        const int fb = c * F4_PER_CHUNK + t * 4;
        float4 o;
        o.x = sb[0]  + off; o.y = sb[1]  + off; o.z = sb[2]  + off; o.w = sb[3]  + off;
        __stcs(yv + fb + 0, o);
        o.x = sb[4]  + off; o.y = sb[5]  + off; o.z = sb[6]  + off; o.w = sb[7]  + off;
        __stcs(yv + fb + 1, o);
        o.x = sb[8]  + off; o.y = sb[9]  + off; o.z = sb[10] + off; o.w = sb[11] + off;
        __stcs(yv + fb + 2, o);
        o.x = sb[12] + off; o.y = sb[13] + off; o.z = sb[14] + off; o.w = sb[15] + off;
        __stcs(yv + fb + 3, o);
    }
}

extern "C" void kernel_launch(void* const* d_in, const int* in_sizes, int n_in,
                              void* d_out, int out_size) {
    const float* x = (const float*)d_in[0];
    float* y = (float*)d_out;

    const int n = out_size;              // 33554432
    const int nseg = n / SEG;            // 4096

    integrator_init_kernel<<<8, 512>>>();
    integrator_scan_kernel<<<nseg, THREADS>>>(x, y);
}